// round 5
// baseline (speedup 1.0000x reference)
#include <cuda_runtime.h>

#define NROWS 65536
#define DOUT  128
#define DLAT  64
#define DZ    64

#define NSMS    152
#define TPB     256
#define NBLOCKS (NSMS * 8)            // 1216 blocks, one wave at 8 blocks/SM
#define T_TOT   (NBLOCKS * TPB)       // 311296

#define ROW_STRIDE (T_TOT / 64)       // 4864 rows per step
// 65536 = 13 * 4864 + 2304
#define ROW_FULL 13
#define ROW_TAIL 2304

#define N_OUT4  (NROWS * DOUT / 4)    // 2097152 = 6 * 311296 + 229376
#define OUT_FULL 6
#define OUT_TAIL 229376

// Zero-initialized device globals (reset by last block each call -> replay-safe)
__device__ float        g_scal[2];      // [0]=KL elem sum, [1]=recon sq sum
__device__ float        g_col[5][DZ];   // Sz, Szt, Sz2, Szt2, Szp
__device__ unsigned int g_count;

__global__ void __launch_bounds__(TPB, 8) vde_fused_kernel(
    const float*  __restrict__ target,
    const float*  __restrict__ output,
    const float*  __restrict__ mean,
    const float*  __restrict__ logv,
    const float*  __restrict__ z,
    const float*  __restrict__ zt,
    float* __restrict__ out)
{
    const int tid  = blockIdx.x * TPB + threadIdx.x;
    const int lane = threadIdx.x & 31;
    const int warp = threadIdx.x >> 5;
    const int col  = tid & 63;          // owned latent column
    const int rb   = tid >> 6;          // starting row, 0..4863

    // ============ unified latent loop: KL + z column stats ====================
    float a = 0.0f;
    float s1 = 0.0f, s2 = 0.0f, s3 = 0.0f, s4 = 0.0f, s5 = 0.0f;
    {
        int idx = rb * 64 + col;
        const int STEP = ROW_STRIDE * 64;
        // 13 full iterations = 6 batches of 2 + 1
        #pragma unroll
        for (int bb = 0; bb < 6; bb++) {
            float lv0 = __ldcs(logv + idx);
            float m0  = __ldcs(mean + idx);
            float u0  = __ldcs(z    + idx);
            float v0  = __ldcs(zt   + idx);
            float lv1 = __ldcs(logv + idx + STEP);
            float m1  = __ldcs(mean + idx + STEP);
            float u1  = __ldcs(z    + idx + STEP);
            float v1  = __ldcs(zt   + idx + STEP);
            a  += lv0 - __expf(lv0) - m0 * m0 + 1.0f;
            s1 += u0; s2 += v0; s3 += u0 * u0; s4 += v0 * v0; s5 += u0 * v0;
            a  += lv1 - __expf(lv1) - m1 * m1 + 1.0f;
            s1 += u1; s2 += v1; s3 += u1 * u1; s4 += v1 * v1; s5 += u1 * v1;
            idx += 2 * STEP;
        }
        {   // iteration 13
            float lv = __ldcs(logv + idx), m = __ldcs(mean + idx);
            float u  = __ldcs(z + idx),    v = __ldcs(zt + idx);
            a  += lv - __expf(lv) - m * m + 1.0f;
            s1 += u; s2 += v; s3 += u * u; s4 += v * v; s5 += u * v;
            idx += STEP;
        }
        if (rb < ROW_TAIL) {   // iteration 14 (partial)
            float lv = __ldcs(logv + idx), m = __ldcs(mean + idx);
            float u  = __ldcs(z + idx),    v = __ldcs(zt + idx);
            a  += lv - __expf(lv) - m * m + 1.0f;
            s1 += u; s2 += v; s3 += u * u; s4 += v * v; s5 += u * v;
        }
    }

    // ============ reconstruction: float4, 6 full + tail =======================
    float b = 0.0f;
    {
        const float4* o4 = (const float4*)output;
        const float4* t4 = (const float4*)target;
        int i = tid;
        #pragma unroll
        for (int k = 0; k < OUT_FULL; k++) {
            float4 oa = __ldcs(o4 + i), ta = __ldcs(t4 + i);
            float d0 = oa.x - ta.x, d1 = oa.y - ta.y;
            float d2 = oa.z - ta.z, d3 = oa.w - ta.w;
            b += d0 * d0 + d1 * d1 + d2 * d2 + d3 * d3;
            i += T_TOT;
        }
        if (tid < OUT_TAIL) {
            float4 oa = __ldcs(o4 + i), ta = __ldcs(t4 + i);
            float d0 = oa.x - ta.x, d1 = oa.y - ta.y;
            float d2 = oa.z - ta.z, d3 = oa.w - ta.w;
            b += d0 * d0 + d1 * d1 + d2 * d2 + d3 * d3;
        }
    }

    // ============ block combine ================================================
    __shared__ float s_col[5][DZ];
    __shared__ float s_ab[2];
    for (int i = threadIdx.x; i < 5 * DZ; i += TPB) ((float*)s_col)[i] = 0.0f;
    if (threadIdx.x < 2) s_ab[threadIdx.x] = 0.0f;
    __syncthreads();

    // 4 threads per column per block -> trivial contention
    atomicAdd(&s_col[0][col], s1);
    atomicAdd(&s_col[1][col], s2);
    atomicAdd(&s_col[2][col], s3);
    atomicAdd(&s_col[3][col], s4);
    atomicAdd(&s_col[4][col], s5);

    #pragma unroll
    for (int off = 16; off; off >>= 1) {
        a += __shfl_down_sync(0xFFFFFFFFu, a, off);
        b += __shfl_down_sync(0xFFFFFFFFu, b, off);
    }
    if (lane == 0) { atomicAdd(&s_ab[0], a); atomicAdd(&s_ab[1], b); }
    __syncthreads();

    for (int i = threadIdx.x; i < 5 * DZ; i += TPB)
        atomicAdd(&((float*)g_col)[i], ((float*)s_col)[i]);
    if (threadIdx.x < 2)
        atomicAdd(&g_scal[threadIdx.x], s_ab[threadIdx.x]);

    // ============ last block finalizes + resets ================================
    __shared__ unsigned int s_rank;
    __threadfence();
    __syncthreads();
    if (threadIdx.x == 0) s_rank = atomicAdd(&g_count, 1u);
    __syncthreads();
    if (s_rank != NBLOCKS - 1) return;

    __threadfence();

    __shared__ float sc[2], ss[2];
    if (threadIdx.x < DZ) {
        const int d = threadIdx.x;
        const float invN = 1.0f / (float)NROWS;
        float Sz   = *((volatile float*)&g_col[0][d]);
        float Szt  = *((volatile float*)&g_col[1][d]);
        float Sz2  = *((volatile float*)&g_col[2][d]);
        float Szt2 = *((volatile float*)&g_col[3][d]);
        float Szp  = *((volatile float*)&g_col[4][d]);

        float mu = Sz * invN, nu = Szt * invN;
        float cov  = Szp * invN - mu * nu;
        float vart = (Sz2  - (float)NROWS * mu * mu) / (float)(NROWS - 1);
        float varu = (Szt2 - (float)NROWS * nu * nu) / (float)(NROWS - 1);
        float sp = sqrtf(fmaxf(vart * varu, 0.0f));

        #pragma unroll
        for (int off = 16; off; off >>= 1) {
            cov += __shfl_down_sync(0xFFFFFFFFu, cov, off);
            sp  += __shfl_down_sync(0xFFFFFFFFu, sp,  off);
        }
        if (lane == 0) { sc[warp] = cov; ss[warp] = sp; }
    }
    __syncthreads();

    if (threadIdx.x == 0) {
        const float invN = 1.0f / (float)NROWS;
        float num = sc[0] + sc[1];
        float dot = ss[0] + ss[1];
        float kl    = -0.5f * (*((volatile float*)&g_scal[0])) * invN;
        float recon = (*((volatile float*)&g_scal[1])) / (float)((long long)NROWS * DOUT);
        out[0] = recon + kl - num / dot;
    }
    __syncthreads();

    for (int i = threadIdx.x; i < 5 * DZ; i += TPB) ((float*)g_col)[i] = 0.0f;
    if (threadIdx.x == 0) { g_scal[0] = 0.0f; g_scal[1] = 0.0f; g_count = 0u; }
}

extern "C" void kernel_launch(void* const* d_in, const int* in_sizes, int n_in,
                              void* d_out, int out_size) {
    (void)in_sizes; (void)n_in; (void)out_size;
    vde_fused_kernel<<<NBLOCKS, TPB>>>(
        (const float*)d_in[0], (const float*)d_in[1],
        (const float*)d_in[2], (const float*)d_in[3],
        (const float*)d_in[4], (const float*)d_in[5],
        (float*)d_out);
}

// round 6
// speedup vs baseline: 1.1383x; 1.1383x over previous
#include <cuda_runtime.h>
#include <cstdint>

#define NROWS 65536
#define DOUT  128
#define DZ    64

#define GRID  608                 // 4 blocks/SM on 152 SMs, one wave
#define TPB   256

#define TILE        1024                       // floats per array per tile
#define TILE_BYTES  (TILE * 4)                 // 4096 B
#define N_LAT_TILES (NROWS * DZ   / TILE)      // 4096 = 6*608 + 448
#define N_REC_TILES (NROWS * DOUT / TILE)      // 8192 = 13*608 + 288
#define LAT_CUT 448
#define REC_CUT 288

// Zero-initialized device globals (reset by last block each call -> replay-safe)
__device__ float        g_scal[2];      // [0]=KL elem sum, [1]=recon sq sum
__device__ float        g_col[5][DZ];   // Sz, Szt, Sz2, Szt2, Szp
__device__ unsigned int g_count;

__device__ __forceinline__ uint32_t smem_u32(const void* p) {
    return (uint32_t)__cvta_generic_to_shared((void*)p);
}
__device__ __forceinline__ void mbar_init(uint32_t a, uint32_t cnt) {
    asm volatile("mbarrier.init.shared.b64 [%0], %1;" :: "r"(a), "r"(cnt) : "memory");
}
__device__ __forceinline__ void mbar_expect(uint32_t a, uint32_t bytes) {
    asm volatile("mbarrier.arrive.expect_tx.shared.b64 _, [%0], %1;"
                 :: "r"(a), "r"(bytes) : "memory");
}
__device__ __forceinline__ void bulk_g2s(uint32_t dst, const float* src,
                                         uint32_t bytes, uint32_t mbar) {
    asm volatile(
        "cp.async.bulk.shared::cluster.global.mbarrier::complete_tx::bytes "
        "[%0], [%1], %2, [%3];"
        :: "r"(dst), "l"(src), "r"(bytes), "r"(mbar) : "memory");
}
__device__ __forceinline__ void mbar_wait(uint32_t a, uint32_t parity) {
    asm volatile(
        "{\n\t"
        ".reg .pred P1;\n\t"
        "LAB_WAIT_%=:\n\t"
        "mbarrier.try_wait.parity.acquire.cta.shared::cta.b64 P1, [%0], %1, 0x989680;\n\t"
        "@P1 bra LAB_DONE_%=;\n\t"
        "bra LAB_WAIT_%=;\n\t"
        "LAB_DONE_%=:\n\t"
        "}"
        :: "r"(a), "r"(parity) : "memory");
}

__global__ void __launch_bounds__(TPB) vde_fused_kernel(
    const float* __restrict__ target,
    const float* __restrict__ output,
    const float* __restrict__ mean,
    const float* __restrict__ logv,
    const float* __restrict__ z,
    const float* __restrict__ zt,
    float* __restrict__ out)
{
    __shared__ __align__(128) float buf[2][4][TILE];     // 32 KB
    __shared__ __align__(8) unsigned long long mbar_s[2];
    __shared__ float s_col[5][DZ];
    __shared__ float s_ab[2];

    const int bid  = blockIdx.x;
    const int t    = threadIdx.x;
    const int lane = t & 31;
    const int warp = t >> 5;
    const int col  = t & 63;

    const uint32_t mb[2] = { smem_u32(&mbar_s[0]), smem_u32(&mbar_s[1]) };

    if (t == 0) { mbar_init(mb[0], 1); mbar_init(mb[1], 1); }
    for (int i = t; i < 5 * DZ; i += TPB) ((float*)s_col)[i] = 0.0f;
    if (t < 2) s_ab[t] = 0.0f;
    __syncthreads();

    const int nlat = (bid < LAT_CUT) ? (N_LAT_TILES / GRID + 1) : (N_LAT_TILES / GRID);
    const int nrec = (bid < REC_CUT) ? (N_REC_TILES / GRID + 1) : (N_REC_TILES / GRID);

    int ph[2] = {0, 0};

    // ---------------- latent phase: lv, m, z, zt per tile ----------------
    // prologue: fill both stages
    if (t == 0) {
        {
            size_t off = (size_t)bid * TILE;
            uint32_t d = smem_u32(&buf[0][0][0]);
            mbar_expect(mb[0], 4 * TILE_BYTES);
            bulk_g2s(d,                  logv + off, TILE_BYTES, mb[0]);
            bulk_g2s(d + 1 * TILE_BYTES, mean + off, TILE_BYTES, mb[0]);
            bulk_g2s(d + 2 * TILE_BYTES, z    + off, TILE_BYTES, mb[0]);
            bulk_g2s(d + 3 * TILE_BYTES, zt   + off, TILE_BYTES, mb[0]);
        }
        if (nlat > 1) {
            size_t off = (size_t)(bid + GRID) * TILE;
            uint32_t d = smem_u32(&buf[1][0][0]);
            mbar_expect(mb[1], 4 * TILE_BYTES);
            bulk_g2s(d,                  logv + off, TILE_BYTES, mb[1]);
            bulk_g2s(d + 1 * TILE_BYTES, mean + off, TILE_BYTES, mb[1]);
            bulk_g2s(d + 2 * TILE_BYTES, z    + off, TILE_BYTES, mb[1]);
            bulk_g2s(d + 3 * TILE_BYTES, zt   + off, TILE_BYTES, mb[1]);
        }
    }

    float a = 0.0f;
    float s1 = 0.0f, s2 = 0.0f, s3 = 0.0f, s4 = 0.0f, s5 = 0.0f;

    for (int k = 0; k < nlat; k++) {
        const int s = k & 1;
        mbar_wait(mb[s], ph[s]); ph[s] ^= 1;

        const float* lv = &buf[s][0][0];
        const float* mm = &buf[s][1][0];
        const float* zz = &buf[s][2][0];
        const float* zb = &buf[s][3][0];
        #pragma unroll
        for (int j = 0; j < 4; j++) {
            const int p = t + j * TPB;
            float l = lv[p], m = mm[p], u = zz[p], v = zb[p];
            a  += l - __expf(l) - m * m + 1.0f;
            s1 += u; s2 += v; s3 += u * u; s4 += v * v; s5 += u * v;
        }
        __syncthreads();

        if (k + 2 < nlat && t == 0) {
            size_t off = (size_t)(bid + (size_t)(k + 2) * GRID) * TILE;
            uint32_t d = smem_u32(&buf[s][0][0]);
            mbar_expect(mb[s], 4 * TILE_BYTES);
            bulk_g2s(d,                  logv + off, TILE_BYTES, mb[s]);
            bulk_g2s(d + 1 * TILE_BYTES, mean + off, TILE_BYTES, mb[s]);
            bulk_g2s(d + 2 * TILE_BYTES, z    + off, TILE_BYTES, mb[s]);
            bulk_g2s(d + 3 * TILE_BYTES, zt   + off, TILE_BYTES, mb[s]);
        }
    }

    // ---------------- recon phase: output, target per tile ----------------
    if (t == 0) {
        {
            size_t off = (size_t)bid * TILE;
            uint32_t d = smem_u32(&buf[0][0][0]);
            mbar_expect(mb[0], 2 * TILE_BYTES);
            bulk_g2s(d,              output + off, TILE_BYTES, mb[0]);
            bulk_g2s(d + TILE_BYTES, target + off, TILE_BYTES, mb[0]);
        }
        if (nrec > 1) {
            size_t off = (size_t)(bid + GRID) * TILE;
            uint32_t d = smem_u32(&buf[1][0][0]);
            mbar_expect(mb[1], 2 * TILE_BYTES);
            bulk_g2s(d,              output + off, TILE_BYTES, mb[1]);
            bulk_g2s(d + TILE_BYTES, target + off, TILE_BYTES, mb[1]);
        }
    }

    float b = 0.0f;
    for (int k = 0; k < nrec; k++) {
        const int s = k & 1;
        mbar_wait(mb[s], ph[s]); ph[s] ^= 1;

        const float* oo = &buf[s][0][0];
        const float* tt = &buf[s][1][0];
        #pragma unroll
        for (int j = 0; j < 4; j++) {
            const int p = t + j * TPB;
            float d = oo[p] - tt[p];
            b += d * d;
        }
        __syncthreads();

        if (k + 2 < nrec && t == 0) {
            size_t off = (size_t)(bid + (size_t)(k + 2) * GRID) * TILE;
            uint32_t d = smem_u32(&buf[s][0][0]);
            mbar_expect(mb[s], 2 * TILE_BYTES);
            bulk_g2s(d,              output + off, TILE_BYTES, mb[s]);
            bulk_g2s(d + TILE_BYTES, target + off, TILE_BYTES, mb[s]);
        }
    }

    // ---------------- block combine ----------------
    atomicAdd(&s_col[0][col], s1);
    atomicAdd(&s_col[1][col], s2);
    atomicAdd(&s_col[2][col], s3);
    atomicAdd(&s_col[3][col], s4);
    atomicAdd(&s_col[4][col], s5);

    #pragma unroll
    for (int off = 16; off; off >>= 1) {
        a += __shfl_down_sync(0xFFFFFFFFu, a, off);
        b += __shfl_down_sync(0xFFFFFFFFu, b, off);
    }
    if (lane == 0) { atomicAdd(&s_ab[0], a); atomicAdd(&s_ab[1], b); }
    __syncthreads();

    for (int i = t; i < 5 * DZ; i += TPB)
        atomicAdd(&((float*)g_col)[i], ((float*)s_col)[i]);
    if (t < 2)
        atomicAdd(&g_scal[t], s_ab[t]);

    // ---------------- last block finalizes + resets ----------------
    __shared__ unsigned int s_rank;
    __threadfence();
    __syncthreads();
    if (t == 0) s_rank = atomicAdd(&g_count, 1u);
    __syncthreads();
    if (s_rank != GRID - 1) return;

    __threadfence();

    __shared__ float sc[2], ss[2];
    if (t < DZ) {
        const int d = t;
        const float invN = 1.0f / (float)NROWS;
        float Sz   = *((volatile float*)&g_col[0][d]);
        float Szt  = *((volatile float*)&g_col[1][d]);
        float Sz2  = *((volatile float*)&g_col[2][d]);
        float Szt2 = *((volatile float*)&g_col[3][d]);
        float Szp  = *((volatile float*)&g_col[4][d]);

        float mu = Sz * invN, nu = Szt * invN;
        float cov  = Szp * invN - mu * nu;
        float vart = (Sz2  - (float)NROWS * mu * mu) / (float)(NROWS - 1);
        float varu = (Szt2 - (float)NROWS * nu * nu) / (float)(NROWS - 1);
        float sp = sqrtf(fmaxf(vart * varu, 0.0f));

        #pragma unroll
        for (int off = 16; off; off >>= 1) {
            cov += __shfl_down_sync(0xFFFFFFFFu, cov, off);
            sp  += __shfl_down_sync(0xFFFFFFFFu, sp,  off);
        }
        if (lane == 0) { sc[warp] = cov; ss[warp] = sp; }
    }
    __syncthreads();

    if (t == 0) {
        const float invN = 1.0f / (float)NROWS;
        float num = sc[0] + sc[1];
        float dot = ss[0] + ss[1];
        float kl    = -0.5f * (*((volatile float*)&g_scal[0])) * invN;
        float recon = (*((volatile float*)&g_scal[1])) / (float)((long long)NROWS * DOUT);
        out[0] = recon + kl - num / dot;
    }
    __syncthreads();

    for (int i = t; i < 5 * DZ; i += TPB) ((float*)g_col)[i] = 0.0f;
    if (t == 0) { g_scal[0] = 0.0f; g_scal[1] = 0.0f; g_count = 0u; }
}

extern "C" void kernel_launch(void* const* d_in, const int* in_sizes, int n_in,
                              void* d_out, int out_size) {
    (void)in_sizes; (void)n_in; (void)out_size;
    vde_fused_kernel<<<GRID, TPB>>>(
        (const float*)d_in[0], (const float*)d_in[1],
        (const float*)d_in[2], (const float*)d_in[3],
        (const float*)d_in[4], (const float*)d_in[5],
        (float*)d_out);
}